// round 11
// baseline (speedup 1.0000x reference)
#include <cuda_runtime.h>

#define DIM   100
#define NW    39
#define NH    4
#define NSLICE 4800
#define NTHR  128          // 4 warps, 1 slice per warp
#define NBLK  (NSLICE / 4) // 1200

__device__ __forceinline__ float sgn035(float t) {
    return __uint_as_float((__float_as_uint(t) & 0x80000000u) | 0x3EB33333u);
}

__global__ __launch_bounds__(NTHR, 6)
void tse_kernel(const float* __restrict__ x,
                const float* __restrict__ w_att,
                const float* __restrict__ b_att,
                float* __restrict__ out)
{
    const int warp  = threadIdx.x >> 5;
    const int lane  = threadIdx.x & 31;
    const int slice = blockIdx.x * (NTHR / 32) + warp;
    const float* __restrict__ xb = x + slice * (40 * DIM);
    const bool act = (lane < 25);
    const int g = lane >> 3;                 // this lane's head group

    // ---- register params: r1 = t*wa, b1 = t*ba, k35 = copysign(0.35, t) ----
    float4 r1[NH], b1[NH], k35;
    #pragma unroll
    for (int h = 0; h < NH; h++) {
        r1[h] = make_float4(0.f, 0.f, 0.f, 0.f);
        b1[h] = make_float4(0.f, 0.f, 0.f, 0.f);
    }
    k35 = make_float4(0.f, 0.f, 0.f, 0.f);
    if (act) {
        const float4 t4 = reinterpret_cast<const float4*>(xb)[lane];
        k35.x = sgn035(t4.x); k35.y = sgn035(t4.y);
        k35.z = sgn035(t4.z); k35.w = sgn035(t4.w);
        #pragma unroll
        for (int h = 0; h < NH; h++) {
            const float4 wv = *reinterpret_cast<const float4*>(w_att + h * DIM + 4 * lane);
            const float4 bv = *reinterpret_cast<const float4*>(b_att + h * DIM + 4 * lane);
            r1[h].x = t4.x * wv.x; r1[h].y = t4.y * wv.y;
            r1[h].z = t4.z * wv.z; r1[h].w = t4.w * wv.w;
            b1[h].x = t4.x * bv.x; b1[h].y = t4.y * bv.y;
            b1[h].z = t4.z * bv.z; b1[h].w = t4.w * bv.w;
        }
    }

    const float* __restrict__ rp = xb + DIM + 4 * lane;

    // relative-order accumulators: acc[j] belongs to head (g ^ j)
    float4 acc[NH];
    #pragma unroll
    for (int j = 0; j < NH; j++) acc[j] = make_float4(0.f, 0.f, 0.f, 0.f);
    float zacc = 0.f;

    // ---- single fused loop over ALL 39 rows (double-buffered loads) ----
    float4 w_cur = make_float4(0.f, 0.f, 0.f, 0.f);
    if (act) w_cur = *reinterpret_cast<const float4*>(rp);

    #pragma unroll 3
    for (int n = 0; n < NW; n++) {
        float4 w_nxt = make_float4(0.f, 0.f, 0.f, 0.f);
        if (act && (n + 1 < NW))
            w_nxt = *reinterpret_cast<const float4*>(rp + (n + 1) * DIM);

        // 4 head-score partials over this lane's 4 d-slots (3 FFMA/elem)
        float a[NH];
        #pragma unroll
        for (int h = 0; h < NH; h++) {
            float y, sa, sb;
            y  = fmaf(w_cur.x, r1[h].x, b1[h].x);
            sa = y * 0.65f;
            sb = k35.x * fabsf(y);
            y  = fmaf(w_cur.y, r1[h].y, b1[h].y);
            sa = fmaf(y, 0.65f, sa);
            sb = fmaf(k35.y, fabsf(y), sb);
            y  = fmaf(w_cur.z, r1[h].z, b1[h].z);
            sa = fmaf(y, 0.65f, sa);
            sb = fmaf(k35.z, fabsf(y), sb);
            y  = fmaf(w_cur.w, r1[h].w, b1[h].w);
            sa = fmaf(y, 0.65f, sa);
            sb = fmaf(k35.w, fabsf(y), sb);
            a[h] = sa + sb;
        }

        // packed butterfly: group total for head g lands on ALL 8 lanes of group g
        const bool lo = (lane < 16);
        float xv = __shfl_xor_sync(0xffffffffu, lo ? a[2] : a[0], 16);
        float yv = __shfl_xor_sync(0xffffffffu, lo ? a[3] : a[1], 16);
        float u0 = (lo ? a[0] : a[2]) + xv;
        float u1 = (lo ? a[1] : a[3]) + yv;
        const bool b3 = (lane & 8) != 0;
        float zv = __shfl_xor_sync(0xffffffffu, b3 ? u0 : u1, 8);
        float t  = (b3 ? u1 : u0) + zv;
        t += __shfl_xor_sync(0xffffffffu, t, 4);
        t += __shfl_xor_sync(0xffffffffu, t, 2);
        t += __shfl_xor_sync(0xffffffffu, t, 1);

        // e for own head; broadcast the other 3 heads' e with 3 shuffles
        const float e0 = __expf(t);
        const float e1 = __shfl_xor_sync(0xffffffffu, e0, 8);    // head g^1
        const float e2 = __shfl_xor_sync(0xffffffffu, e0, 16);   // head g^2
        const float e3 = __shfl_xor_sync(0xffffffffu, e1, 16);   // head g^3

        // accumulate weighted row (w_cur still live in registers)
        acc[0].x = fmaf(e0, w_cur.x, acc[0].x); acc[0].y = fmaf(e0, w_cur.y, acc[0].y);
        acc[0].z = fmaf(e0, w_cur.z, acc[0].z); acc[0].w = fmaf(e0, w_cur.w, acc[0].w);
        acc[1].x = fmaf(e1, w_cur.x, acc[1].x); acc[1].y = fmaf(e1, w_cur.y, acc[1].y);
        acc[1].z = fmaf(e1, w_cur.z, acc[1].z); acc[1].w = fmaf(e1, w_cur.w, acc[1].w);
        acc[2].x = fmaf(e2, w_cur.x, acc[2].x); acc[2].y = fmaf(e2, w_cur.y, acc[2].y);
        acc[2].z = fmaf(e2, w_cur.z, acc[2].z); acc[2].w = fmaf(e2, w_cur.w, acc[2].w);
        acc[3].x = fmaf(e3, w_cur.x, acc[3].x); acc[3].y = fmaf(e3, w_cur.y, acc[3].y);
        acc[3].z = fmaf(e3, w_cur.z, acc[3].z); acc[3].w = fmaf(e3, w_cur.w, acc[3].w);
        zacc += e0;

        w_cur = w_nxt;
    }

    // ---- gather all heads' Z, normalize, store (no smem, no barriers) ----
    const float z0 = zacc;                                   // head g
    const float z1 = __shfl_xor_sync(0xffffffffu, z0, 8);    // head g^1
    const float z2 = __shfl_xor_sync(0xffffffffu, z0, 16);   // head g^2
    const float z3 = __shfl_xor_sync(0xffffffffu, z1, 16);   // head g^3

    if (act) {
        float* ob = out + slice * (NH * DIM);
        const float inv[NH] = { 1.f / z0, 1.f / z1, 1.f / z2, 1.f / z3 };
        #pragma unroll
        for (int j = 0; j < NH; j++) {
            const int h = g ^ j;
            float4 v = acc[j];
            v.x *= inv[j]; v.y *= inv[j]; v.z *= inv[j]; v.w *= inv[j];
            *reinterpret_cast<float4*>(ob + h * DIM + 4 * lane) = v;
        }
    }
}

extern "C" void kernel_launch(void* const* d_in, const int* in_sizes, int n_in,
                              void* d_out, int out_size)
{
    const float* x     = (const float*)d_in[0];
    const float* w_att = (const float*)d_in[1];
    const float* b_att = (const float*)d_in[2];
    float* out = (float*)d_out;
    tse_kernel<<<NBLK, NTHR>>>(x, w_att, b_att, out);
}